// round 14
// baseline (speedup 1.0000x reference)
#include <cuda_runtime.h>

#define BN_EPS 1e-5f
#define MAX_E 1000000

// ---- device scratch (allocation-free: __device__ globals) ----
static __device__ float g_h[(size_t)MAX_E * 64];   // h1 / h2 scratch [E,64]
static __device__ float g_Wt1[64 * 256];           // W1 transposed [f][k]
static __device__ float g_Wt2[64 * 64];            // folded+transposed W2'
static __device__ float g_Wt3[64 * 64];            // folded+transposed W3'
static __device__ float g_bf2[64];
static __device__ float g_bf3[64];
static __device__ float g_sum[3][64];
static __device__ float g_sq[3][64];
static __device__ float g_s3[64];
static __device__ float g_t3[64];
static __device__ int   g_is64;                    // batch dtype flag (1 = int64)

// ---- packed fp32x2 FMA (Blackwell FFMA2) ----
__device__ __forceinline__ void ffma2(unsigned long long& d, unsigned long long a,
                                      unsigned long long b) {
    asm("fma.rn.f32x2 %0, %1, %2, %0;" : "+l"(d) : "l"(a), "l"(b));
}
__device__ __forceinline__ float2 unpack_f32x2(unsigned long long v) {
    float2 r;
    asm("mov.b64 {%0, %1}, %2;" : "=f"(r.x), "=f"(r.y) : "l"(v));
    return r;
}
__device__ __forceinline__ unsigned smem_u32(const void* p) {
    return (unsigned)__cvta_generic_to_shared(p);
}
__device__ __forceinline__ void cp16(unsigned dst, const void* src) {
    asm volatile("cp.async.cg.shared.global [%0], [%1], 16;" :: "r"(dst), "l"(src));
}
__device__ __forceinline__ void cp_commit() {
    asm volatile("cp.async.commit_group;" ::: "memory");
}
template <int N>
__device__ __forceinline__ void cp_wait() {
    asm volatile("cp.async.wait_group %0;" :: "n"(N) : "memory");
}

// ---- prep: zero stats, detect batch dtype, transpose W1 ----
__global__ void prep_kernel(const float* __restrict__ W1, const void* __restrict__ batch,
                            int E, int G) {
    if (blockIdx.x == 0) {
        float* s = &g_sum[0][0];
        float* q = &g_sq[0][0];
        for (int i = threadIdx.x; i < 192; i += blockDim.x) { s[i] = 0.f; q[i] = 0.f; }
        if (threadIdx.x == 0) {
            // int64 view of an int32 buffer packs two words -> values >= G
            const long long* b64 = (const long long*)batch;
            int n = (E < 64) ? E : 64;
            int ok = 1;
            for (int i = 0; i < n; i++) {
                long long v = b64[i];
                if (v < 0 || v >= (long long)G) { ok = 0; break; }
            }
            g_is64 = ok;
        }
    }
    int tid = blockIdx.x * blockDim.x + threadIdx.x;
    for (int i = tid; i < 64 * 256; i += gridDim.x * blockDim.x) {
        int j = i >> 8, k = i & 255;
        g_Wt1[i] = W1[k * 64 + j];
    }
}

// ---- fold BN(layer LAYER) into next layer's weights ----
template <int LAYER>
__global__ void fold_kernel(const float* __restrict__ Wn, const float* __restrict__ bn,
                            const float* __restrict__ gamma, const float* __restrict__ beta,
                            float Einv) {
    __shared__ float s[64], t[64];
    int j = threadIdx.x;
    float mean = g_sum[LAYER][j] * Einv;
    float var  = g_sq[LAYER][j] * Einv - mean * mean;
    float sc = gamma[j] / sqrtf(var + BN_EPS);
    s[j] = sc;
    t[j] = beta[j] - mean * sc;
    __syncthreads();
    float* WtOut = (LAYER == 0) ? g_Wt2 : g_Wt3;
    float* bOut  = (LAYER == 0) ? g_bf2 : g_bf3;
    float bacc = bn[j];
#pragma unroll
    for (int k = 0; k < 64; k++) {
        float w = Wn[k * 64 + j];
        WtOut[j * 64 + k] = w * s[k];   // transposed + BN-scaled
        bacc += t[k] * w;
    }
    bOut[j] = bacc;
}

__global__ void fin_kernel(const float* __restrict__ gamma, const float* __restrict__ beta,
                           float Einv) {
    int j = threadIdx.x;
    float mean = g_sum[2][j] * Einv;
    float var  = g_sq[2][j] * Einv - mean * mean;
    float sc = gamma[j] / sqrtf(var + BN_EPS);
    g_s3[j] = sc;
    g_t3[j] = beta[j] - mean * sc;
}

__global__ void affine_kernel(float* __restrict__ out, int n4) {
    __shared__ float s[64], t[64];
    if (threadIdx.x < 64) { s[threadIdx.x] = g_s3[threadIdx.x]; t[threadIdx.x] = g_t3[threadIdx.x]; }
    __syncthreads();
    float4* o4 = reinterpret_cast<float4*>(out);
    for (int i = blockIdx.x * blockDim.x + threadIdx.x; i < n4; i += gridDim.x * blockDim.x) {
        float4 v = o4[i];
        int fb = (i & 15) << 2;
        v.x = v.x * s[fb] + t[fb];
        v.y = v.y * s[fb + 1] + t[fb + 1];
        v.z = v.z * s[fb + 2] + t[fb + 2];
        v.w = v.w * s[fb + 3] + t[fb + 3];
        o4[i] = v;
    }
}

// ---- stage one 64-k chunk of one 256-edge tile via cp.async ----
// 512 threads: thread pair (2r, 2r+1) stages row r; each thread one 128B half.
template <int LAYER>
__device__ __forceinline__ void stage_chunk(float* Adst, int t, int c,
                                            const float* in0, const float* in1,
                                            const float* in2, const float* ga,
                                            long long myB, int E, int tid) {
    int r2 = tid >> 1, half = tid & 1;
    int row = t * 256 + r2;
    if (row >= E) row = E - 1;        // duplicate tail row; epilogue guards stores
    if (row < 0) row = 0;
    const float4* g;
    if (LAYER == 0) {
        if (c == 3) {
            g = (const float4*)ga + (size_t)myB * 16;
        } else {
            const float* s = (c == 0) ? in0 : (c == 1) ? in1 : in2;
            g = (const float4*)s + (size_t)row * 16;
        }
    } else {
        g = (const float4*)g_h + (size_t)row * 16;
    }
    g += half * 8;
    unsigned sa = smem_u32(Adst + r2 * 68 + half * 32);
#pragma unroll
    for (int m = 0; m < 8; m++) cp16(sa + m * 16, g + m);
}

__device__ __forceinline__ long long load_batch_idx(const void* batch, int row, int G) {
    long long b = g_is64 ? ((const long long*)batch)[row]
                         : (long long)((const int*)batch)[row];
    if (b < 0) b = 0;
    if (b >= (long long)G) b = G - 1;
    return b;
}

// ---- persistent fused GEMM + relu + stats kernel ----
// 1 block/SM, 512 threads (16 warps = 4/SMSP). Tile = 256 edges x 64 f.
// Warp grid: wy = warp>>1 (8 edge groups of 32), wx = warp&1 (2 f halves).
// Thread tile 8x4: e = wy*32 + ty + 4i (i<8), f = wx*32 + tx + 8j (j<4),
// tx = lane&7, ty = lane>>3. Fragments via LDS.64 (2 k per load) to keep
// register pressure ~110 < 128 so ptxas retains the load-block/FMA-block
// schedule. f32x2 lanes carry (even k, odd k) partial sums.
template <int NCH, int LAYER>
__global__ void __launch_bounds__(512, 1)
layer_kernel(const float* __restrict__ in0, const float* __restrict__ in1,
             const float* __restrict__ in2, const float* __restrict__ ga,
             const void* __restrict__ batch, const float* __restrict__ bias1,
             float* __restrict__ outParam, int E, int G) {
    constexpr int KDIM = NCH * 64;
    constexpr int WP = KDIM + 4;   // W pitch (floats): bank stride 4
    constexpr int AP = 68;         // A pitch (floats)
    extern __shared__ float sm[];
    float* Ws   = sm;                    // [64][WP]
    float* Abuf = sm + 64 * WP;          // [2][256][AP]
    __shared__ float bs[64], ssum[64], ssq[64];

    const float* Wt   = (LAYER == 0) ? g_Wt1 : (LAYER == 1) ? g_Wt2 : g_Wt3;
    const float* bias = (LAYER == 0) ? bias1 : (LAYER == 1) ? g_bf2 : g_bf3;
    float* outp = (LAYER == 2) ? outParam : g_h;

    int tid = threadIdx.x;
    int warp = tid >> 5, lane = tid & 31;
    int wx = warp & 1, wy = warp >> 1;
    int tx = lane & 7, ty = lane >> 3;

    // W -> smem once per block (float4-coalesced)
    {
        const float4* w4 = (const float4*)Wt;
        for (int i = tid; i < 64 * KDIM / 4; i += 512) {
            int j = i / (KDIM / 4), m = i - j * (KDIM / 4);
            *(float4*)&Ws[j * WP + m * 4] = w4[i];
        }
    }
    if (tid < 64) { bs[tid] = bias[tid]; ssum[tid] = 0.f; ssq[tid] = 0.f; }

    int nt = (E + 255) >> 8;
    int nb = gridDim.x;

    unsigned long long acc[8][4];
#pragma unroll
    for (int i = 0; i < 8; i++)
#pragma unroll
        for (int j = 0; j < 4; j++) acc[i][j] = 0ull;
    float ls[4], lq[4];
#pragma unroll
    for (int j = 0; j < 4; j++) { ls[j] = 0.f; lq[j] = 0.f; }

    int t0 = blockIdx.x;
    if (t0 < nt) {
        long long myB = 0;
        if (LAYER == 0) {
            int r = t0 * 256 + (tid >> 1);
            if (r >= E) r = E - 1;
            myB = load_batch_idx(batch, r, G);
        }

        // prologue: stage (t0, chunk 0) into buffer 0
        stage_chunk<LAYER>(Abuf, t0, 0, in0, in1, in2, ga, myB, E, tid);
        cp_commit();

        int up = 0;  // buffer parity of current compute unit
        for (int t = t0; t < nt; t += nb) {
#pragma unroll 1
            for (int c = 0; c < NCH; c++) {
                int tn = (c + 1 < NCH) ? t : t + nb;
                int cn = (c + 1 < NCH) ? c + 1 : 0;
                bool hn = (tn < nt);
                if (hn) {
                    stage_chunk<LAYER>(Abuf + (up ^ 1) * 256 * AP, tn, cn,
                                       in0, in1, in2, ga, myB, E, tid);
                    cp_commit();
                    cp_wait<1>();
                } else {
                    cp_wait<0>();
                }
                __syncthreads();

                const float* Ab = Abuf + up * 256 * AP + (wy * 32 + ty) * AP;
                const float* Wb = Ws + (wx * 32 + tx) * WP + c * 64;
#pragma unroll 4
                for (int kk = 0; kk < 64; kk += 2) {
                    unsigned long long av[8], wv[4];
#pragma unroll
                    for (int i = 0; i < 8; i++)
                        av[i] = *(const unsigned long long*)(Ab + i * 4 * AP + kk);
#pragma unroll
                    for (int j = 0; j < 4; j++)
                        wv[j] = *(const unsigned long long*)(Wb + j * 8 * WP + kk);
#pragma unroll
                    for (int i = 0; i < 8; i++)
#pragma unroll
                        for (int j = 0; j < 4; j++) ffma2(acc[i][j], av[i], wv[j]);
                }

                if (c == NCH - 1) {
                    int eb = t * 256 + wy * 32 + ty;
#pragma unroll
                    for (int i = 0; i < 8; i++) {
                        int ge = eb + 4 * i;
                        bool ok = ge < E;
#pragma unroll
                        for (int j = 0; j < 4; j++) {
                            float2 p = unpack_f32x2(acc[i][j]);
                            acc[i][j] = 0ull;
                            int f = wx * 32 + tx + 8 * j;
                            float v = fmaxf(p.x + p.y + bs[f], 0.f);
                            if (ok) {
                                outp[(size_t)ge * 64 + f] = v;
                                ls[j] += v;
                                lq[j] += v * v;
                            }
                        }
                    }
                }
                __syncthreads();   // protect buf[up] before reuse as cp.async dst

                if (LAYER == 0 && hn && cn == 0) {  // next tile's gather indices
                    int r = tn * 256 + (tid >> 1);
                    if (r >= E) r = E - 1;
                    myB = load_batch_idx(batch, r, G);
                }
                up ^= 1;
            }
        }
    }

    // stats: reduce over ty within warp (lane bits 3,4), then smem atomics
#pragma unroll
    for (int j = 0; j < 4; j++) {
        ls[j] += __shfl_xor_sync(0xffffffffu, ls[j], 8);
        ls[j] += __shfl_xor_sync(0xffffffffu, ls[j], 16);
        lq[j] += __shfl_xor_sync(0xffffffffu, lq[j], 8);
        lq[j] += __shfl_xor_sync(0xffffffffu, lq[j], 16);
    }
    if (ty == 0) {
#pragma unroll
        for (int j = 0; j < 4; j++) {
            int f = wx * 32 + tx + 8 * j;
            atomicAdd(&ssum[f], ls[j]);
            atomicAdd(&ssq[f], lq[j]);
        }
    }
    __syncthreads();
    if (tid < 64) {
        atomicAdd(&g_sum[LAYER][tid], ssum[tid]);
        atomicAdd(&g_sq[LAYER][tid], ssq[tid]);
    }
}

extern "C" void kernel_launch(void* const* d_in, const int* in_sizes, int n_in,
                              void* d_out, int out_size) {
    const float* src   = (const float*)d_in[0];
    const float* dst   = (const float*)d_in[1];
    const float* eat   = (const float*)d_in[2];
    const float* gat   = (const float*)d_in[3];
    const void*  batch = d_in[4];
    const float* W1 = (const float*)d_in[5];
    const float* b1 = (const float*)d_in[6];
    const float* W2 = (const float*)d_in[7];
    const float* b2 = (const float*)d_in[8];
    const float* W3 = (const float*)d_in[9];
    const float* b3 = (const float*)d_in[10];
    const float* g1 = (const float*)d_in[11];
    const float* be1 = (const float*)d_in[12];
    const float* g2 = (const float*)d_in[13];
    const float* be2 = (const float*)d_in[14];
    const float* g3 = (const float*)d_in[15];
    const float* be3 = (const float*)d_in[16];

    int E = in_sizes[0] / 64;
    int G = in_sizes[3] / 64;
    float Einv = 1.0f / (float)E;
    float* out = (float*)d_out;

    int nsm = 148;
    cudaDeviceGetAttribute(&nsm, cudaDevAttrMultiProcessorCount, 0);  // pure query, capture-safe
    if (nsm < 1) nsm = 148;
    int nt = (E + 255) >> 8;
    int nb = (nsm < nt) ? nsm : nt;
    if (nb < 1) nb = 1;

    constexpr int SM1 = (64 * 260 + 2 * 256 * 68) * 4;  // 205,824 B
    constexpr int SMN = (64 * 68 + 2 * 256 * 68) * 4;   // 156,672 B
    cudaFuncSetAttribute(layer_kernel<4, 0>, cudaFuncAttributeMaxDynamicSharedMemorySize, SM1);
    cudaFuncSetAttribute(layer_kernel<1, 1>, cudaFuncAttributeMaxDynamicSharedMemorySize, SMN);
    cudaFuncSetAttribute(layer_kernel<1, 2>, cudaFuncAttributeMaxDynamicSharedMemorySize, SMN);

    prep_kernel<<<16, 256>>>(W1, batch, E, G);

    // layer 1: concat(src,dest,edge,global[batch]) @ W1 + b1 -> relu -> g_h, stats[0]
    layer_kernel<4, 0><<<nb, 512, SM1>>>(src, dst, eat, gat, batch, b1, out, E, G);
    fold_kernel<0><<<1, 64>>>(W2, b2, g1, be1, Einv);

    // layer 2: g_h @ W2' + b2' -> relu -> g_h, stats[1]
    layer_kernel<1, 1><<<nb, 512, SMN>>>(src, dst, eat, gat, batch, b1, out, E, G);
    fold_kernel<1><<<1, 64>>>(W3, b3, g2, be2, Einv);

    // layer 3: g_h @ W3' + b3' -> relu -> d_out (pre-BN), stats[2]
    layer_kernel<1, 2><<<nb, 512, SMN>>>(src, dst, eat, gat, batch, b1, out, E, G);
    fin_kernel<<<1, 64>>>(g3, be3, Einv);

    // final BN affine in place on d_out
    affine_kernel<<<4096, 256>>>(out, E * 16);
}

// round 16
// speedup vs baseline: 1.3618x; 1.3618x over previous
#include <cuda_runtime.h>
#include <cuda_bf16.h>

#define BN_EPS 1e-5f
#define MAX_E 1000000

// ---- device scratch (allocation-free) ----
static __device__ __align__(128) __nv_bfloat16 g_hh[(size_t)MAX_E * 64];  // h hi
static __device__ __align__(128) __nv_bfloat16 g_hl[(size_t)MAX_E * 64];  // h lo
static __device__ __align__(128) __nv_bfloat16 g_W1s[8 * 4096];  // [chunk][hi|lo][4096] swizzled
static __device__ __align__(128) __nv_bfloat16 g_W2s[2 * 4096];
static __device__ __align__(128) __nv_bfloat16 g_W3s[2 * 4096];
static __device__ float g_bf2[64], g_bf3[64];
static __device__ float g_sum[3][64], g_sq[3][64], g_s3[64], g_t3[64];
static __device__ int   g_is64;

// ---- helpers ----
__device__ __forceinline__ unsigned smem_u32(const void* p) {
    return (unsigned)__cvta_generic_to_shared(p);
}
__device__ __forceinline__ void cp16(unsigned dst, const void* src) {
    asm volatile("cp.async.cg.shared.global [%0], [%1], 16;" :: "r"(dst), "l"(src));
}
__device__ __forceinline__ void cp_commit() { asm volatile("cp.async.commit_group;" ::: "memory"); }
template <int N> __device__ __forceinline__ void cp_wait() {
    asm volatile("cp.async.wait_group %0;" :: "n"(N) : "memory");
}
__device__ __forceinline__ unsigned swz(unsigned o) { return o ^ ((o >> 3) & 0x70); }
__device__ __forceinline__ unsigned packbf(float lo, float hi) {
    unsigned r;
    asm("cvt.rn.bf16x2.f32 %0, %1, %2;" : "=r"(r) : "f"(hi), "f"(lo));  // upper=hi word
    return r;
}
__device__ __forceinline__ void ldsm4(unsigned* r, unsigned a) {
    asm volatile("ldmatrix.sync.aligned.m8n8.x4.shared.b16 {%0,%1,%2,%3}, [%4];"
                 : "=r"(r[0]), "=r"(r[1]), "=r"(r[2]), "=r"(r[3]) : "r"(a));
}
__device__ __forceinline__ void mma16816(float* c, const unsigned* a, const unsigned* b) {
    asm volatile("mma.sync.aligned.m16n8k16.row.col.f32.bf16.bf16.f32 "
                 "{%0,%1,%2,%3}, {%4,%5,%6,%7}, {%8,%9}, {%0,%1,%2,%3};"
                 : "+f"(c[0]), "+f"(c[1]), "+f"(c[2]), "+f"(c[3])
                 : "r"(a[0]), "r"(a[1]), "r"(a[2]), "r"(a[3]), "r"(b[0]), "r"(b[1]));
}
__device__ __forceinline__ long long load_bidx(const void* b, int row, int G) {
    long long v = g_is64 ? ((const long long*)b)[row] : (long long)((const int*)b)[row];
    if (v < 0) v = 0;
    if (v >= (long long)G) v = G - 1;
    return v;
}

// ---- prep: zero stats, dtype probe, W1 -> split+swizzled tiles ----
__global__ void prep_kernel(const float* __restrict__ W1, const void* __restrict__ batch,
                            int E, int G) {
    if (blockIdx.x == 0) {
        float* s = &g_sum[0][0];
        float* q = &g_sq[0][0];
        for (int i = threadIdx.x; i < 192; i += blockDim.x) { s[i] = 0.f; q[i] = 0.f; }
        if (threadIdx.x == 0) {
            const long long* b64 = (const long long*)batch;
            int n = (E < 64) ? E : 64, ok = 1;
            for (int i = 0; i < n; i++) {
                long long v = b64[i];
                if (v < 0 || v >= (long long)G) { ok = 0; break; }
            }
            g_is64 = ok;
        }
    }
    int tid = blockIdx.x * blockDim.x + threadIdx.x;
    for (int i = tid; i < 64 * 256; i += gridDim.x * blockDim.x) {
        int j = i >> 8, k = i & 255;                 // f, global k
        float w = W1[k * 64 + j];                    // transpose on the fly
        __nv_bfloat16 h = __float2bfloat16(w);
        __nv_bfloat16 l = __float2bfloat16(w - __bfloat162float(h));
        int c = k >> 6, kk = k & 63;
        unsigned off = swz((unsigned)(j * 128 + kk * 2)) >> 1;
        g_W1s[c * 8192 + off] = h;
        g_W1s[c * 8192 + 4096 + off] = l;
    }
}

// ---- fold BN(LAYER) into next weights -> split+swizzled tiles ----
template <int LAYER>
__global__ void fold_kernel(const float* __restrict__ Wn, const float* __restrict__ bn,
                            const float* __restrict__ gamma, const float* __restrict__ beta,
                            float Einv) {
    __shared__ float s[64], t[64];
    int j = threadIdx.x;
    float mean = g_sum[LAYER][j] * Einv;
    float var  = g_sq[LAYER][j] * Einv - mean * mean;
    float sc = gamma[j] / sqrtf(var + BN_EPS);
    s[j] = sc;
    t[j] = beta[j] - mean * sc;
    __syncthreads();
    __nv_bfloat16* Wd = (LAYER == 0) ? g_W2s : g_W3s;
    float* bO = (LAYER == 0) ? g_bf2 : g_bf3;
    float bacc = bn[j];
#pragma unroll
    for (int k = 0; k < 64; k++) {
        float w0 = Wn[k * 64 + j];
        float w = w0 * s[k];
        bacc += t[k] * w0;
        __nv_bfloat16 h = __float2bfloat16(w);
        __nv_bfloat16 l = __float2bfloat16(w - __bfloat162float(h));
        unsigned off = swz((unsigned)(j * 128 + k * 2)) >> 1;
        Wd[off] = h;
        Wd[4096 + off] = l;
    }
    bO[j] = bacc;
}

__global__ void fin_kernel(const float* __restrict__ gamma, const float* __restrict__ beta,
                           float Einv) {
    int j = threadIdx.x;
    float mean = g_sum[2][j] * Einv;
    float var  = g_sq[2][j] * Einv - mean * mean;
    float sc = gamma[j] / sqrtf(var + BN_EPS);
    g_s3[j] = sc;
    g_t3[j] = beta[j] - mean * sc;
}

__global__ void affine_kernel(float* __restrict__ out, int n4) {
    __shared__ float s[64], t[64];
    if (threadIdx.x < 64) { s[threadIdx.x] = g_s3[threadIdx.x]; t[threadIdx.x] = g_t3[threadIdx.x]; }
    __syncthreads();
    float4* o4 = reinterpret_cast<float4*>(out);
    for (int i = blockIdx.x * blockDim.x + threadIdx.x; i < n4; i += gridDim.x * blockDim.x) {
        float4 v = o4[i];
        int fb = (i & 15) << 2;
        v.x = v.x * s[fb] + t[fb];
        v.y = v.y * s[fb + 1] + t[fb + 1];
        v.z = v.z * s[fb + 2] + t[fb + 2];
        v.w = v.w * s[fb + 3] + t[fb + 3];
        o4[i] = v;
    }
}

// ---- HMMA layer: one 128-thread block per 128-edge x 64-f tile ----
// mma.sync m16n8k16 bf16, hi/lo split: D = Ah*Wh + Ah*Wl + Al*Wh (f32 reg accum).
// Warp w: rows w*32..w*32+31 (2 m-tiles), all 64 f (8 n-tiles), k in 16-steps.
// smem: [W: NCH*16KB (hi|lo per chunk, swizzled)][A hi 16KB | lo 16KB] = sE 33,280B reuse.
template <int NCH, int LAYER>
__global__ void __launch_bounds__(128)
mma_layer(const float* __restrict__ in0, const float* __restrict__ in1,
          const float* __restrict__ in2, const float* __restrict__ ga,
          const void* __restrict__ batch, const float* __restrict__ bias1,
          float* __restrict__ outP, int E, int G) {
    extern __shared__ char dyn[];
    __shared__ float bs[64];
    unsigned dynb = smem_u32(dyn);
    unsigned ab = (dynb + 1023u) & ~1023u;
    char* abp = dyn + (ab - dynb);
    const unsigned aoff = NCH * 16384u;
    int tid = threadIdx.x, warp = tid >> 5, lane = tid & 31;

    if (tid < 64)
        bs[tid] = ((LAYER == 0) ? bias1 : (LAYER == 1) ? g_bf2 : g_bf3)[tid];

    // stage W tiles (pre-swizzled, contiguous)
    {
        const char* ws = (LAYER == 0) ? (const char*)g_W1s
                       : (LAYER == 1) ? (const char*)g_W2s : (const char*)g_W3s;
        for (int i = tid; i < NCH * 1024; i += 128) cp16(ab + i * 16u, ws + (size_t)i * 16);
    }
    cp_commit();

    int e0 = blockIdx.x * 128;
    int row = e0 + tid;
    if (row >= E) row = E - 1;

    float acc[2][8][4];
#pragma unroll
    for (int mi = 0; mi < 2; mi++)
#pragma unroll
        for (int nt = 0; nt < 8; nt++)
#pragma unroll
            for (int u = 0; u < 4; u++) acc[mi][nt][u] = 0.f;

    // ldmatrix lane geometry
    int m0 = warp * 32;
    int arr = lane & 15, akc = lane >> 4;               // A: row off, k-half
    int bnr = (lane & 7) + ((lane >> 4) << 3);          // B: n off
    int bkc = (lane >> 3) & 1;                          // B: k-half
    unsigned aAH = ab + aoff, aAL = aAH + 16384u;

    if (NCH == 1) {
        const char* hs = (const char*)g_hh + (size_t)row * 128;
        const char* ls = (const char*)g_hl + (size_t)row * 128;
#pragma unroll
        for (int m = 0; m < 8; m++) {
            unsigned so = swz((unsigned)(tid * 128 + m * 16));
            cp16(aAH + so, hs + m * 16);
            cp16(aAL + so, ls + m * 16);
        }
        cp_commit();
        cp_wait<0>();
        __syncthreads();
#pragma unroll
        for (int s = 0; s < 3; s++) {
            unsigned abase = (s == 2) ? aAL : aAH;
            unsigned wbase = ab + ((s == 1) ? 8192u : 0u);
#pragma unroll
            for (int k = 0; k < 4; k++) {
                unsigned a0[4], a1[4];
                ldsm4(a0, abase + swz((unsigned)((m0 + arr) * 128 + k * 32 + akc * 16)));
                ldsm4(a1, abase + swz((unsigned)((m0 + 16 + arr) * 128 + k * 32 + akc * 16)));
#pragma unroll
                for (int np = 0; np < 4; np++) {
                    unsigned bf[4];
                    ldsm4(bf, wbase + swz((unsigned)((np * 16 + bnr) * 128 + k * 32 + bkc * 16)));
                    mma16816(acc[0][2 * np], a0, bf);
                    mma16816(acc[0][2 * np + 1], a0, bf + 2);
                    mma16816(acc[1][2 * np], a1, bf);
                    mma16816(acc[1][2 * np + 1], a1, bf + 2);
                }
            }
        }
    } else {
        cp_wait<0>();   // W resident
        long long b = load_bidx(batch, row, G);
#pragma unroll 1
        for (int c = 0; c < 4; c++) {
            const float* s = (c == 0) ? in0 : (c == 1) ? in1 : (c == 2) ? in2 : ga;
            const float4* s4 = (const float4*)(s + ((c == 3) ? (size_t)b : (size_t)row) * 64);
            float4 x[16];
#pragma unroll
            for (int m = 0; m < 16; m++) x[m] = s4[m];
            __syncthreads();   // previous chunk's ldmatrix reads done
#pragma unroll
            for (int g = 0; g < 8; g++) {
                float4 p0 = x[2 * g], p1 = x[2 * g + 1];
                unsigned h0 = packbf(p0.x, p0.y), h1 = packbf(p0.z, p0.w);
                unsigned h2 = packbf(p1.x, p1.y), h3 = packbf(p1.z, p1.w);
                uint4 hv = make_uint4(h0, h1, h2, h3);
                uint4 lv = make_uint4(
                    packbf(p0.x - __uint_as_float(h0 << 16), p0.y - __uint_as_float(h0 & 0xffff0000u)),
                    packbf(p0.z - __uint_as_float(h1 << 16), p0.w - __uint_as_float(h1 & 0xffff0000u)),
                    packbf(p1.x - __uint_as_float(h2 << 16), p1.y - __uint_as_float(h2 & 0xffff0000u)),
                    packbf(p1.z - __uint_as_float(h3 << 16), p1.w - __uint_as_float(h3 & 0xffff0000u)));
                unsigned so = swz((unsigned)(tid * 128 + g * 16));
                *(uint4*)(abp + aoff + so) = hv;
                *(uint4*)(abp + aoff + 16384u + so) = lv;
            }
            __syncthreads();
            unsigned wb = ab + (unsigned)c * 16384u;
#pragma unroll
            for (int s2 = 0; s2 < 3; s2++) {
                unsigned abase = (s2 == 2) ? aAL : aAH;
                unsigned wbase = wb + ((s2 == 1) ? 8192u : 0u);
#pragma unroll
                for (int k = 0; k < 4; k++) {
                    unsigned a0[4], a1[4];
                    ldsm4(a0, abase + swz((unsigned)((m0 + arr) * 128 + k * 32 + akc * 16)));
                    ldsm4(a1, abase + swz((unsigned)((m0 + 16 + arr) * 128 + k * 32 + akc * 16)));
#pragma unroll
                    for (int np = 0; np < 4; np++) {
                        unsigned bf[4];
                        ldsm4(bf, wbase + swz((unsigned)((np * 16 + bnr) * 128 + k * 32 + bkc * 16)));
                        mma16816(acc[0][2 * np], a0, bf);
                        mma16816(acc[0][2 * np + 1], a0, bf + 2);
                        mma16816(acc[1][2 * np], a1, bf);
                        mma16816(acc[1][2 * np + 1], a1, bf + 2);
                    }
                }
            }
        }
    }

    // ---- epilogue: acc -> sE (relu+bias), outputs, stats ----
    __syncthreads();   // all ldmatrix reads of A region complete before sE reuse
    float* sE = (float*)(abp + aoff);
#pragma unroll
    for (int mi = 0; mi < 2; mi++) {
        int r = m0 + mi * 16 + (lane >> 2);
        bool ok0 = (e0 + r) < E, ok1 = (e0 + r + 8) < E;
#pragma unroll
        for (int nt = 0; nt < 8; nt++) {
            int cc = nt * 8 + (lane & 3) * 2;
            float v0 = ok0 ? fmaxf(acc[mi][nt][0] + bs[cc], 0.f) : 0.f;
            float v1 = ok0 ? fmaxf(acc[mi][nt][1] + bs[cc + 1], 0.f) : 0.f;
            float v2 = ok1 ? fmaxf(acc[mi][nt][2] + bs[cc], 0.f) : 0.f;
            float v3 = ok1 ? fmaxf(acc[mi][nt][3] + bs[cc + 1], 0.f) : 0.f;
            sE[r * 65 + cc] = v0;
            sE[r * 65 + cc + 1] = v1;
            sE[(r + 8) * 65 + cc] = v2;
            sE[(r + 8) * 65 + cc + 1] = v3;
        }
    }
    __syncthreads();

    int e = e0 + tid;
    bool ok = e < E;
    const float* myE = sE + tid * 65;
    if (LAYER < 2) {
        if (ok) {
#pragma unroll
            for (int cb = 0; cb < 64; cb += 8) {
                unsigned hw[4], lw[4];
#pragma unroll
                for (int u = 0; u < 4; u++) {
                    float v0 = myE[cb + 2 * u], v1 = myE[cb + 2 * u + 1];
                    unsigned h = packbf(v0, v1);
                    hw[u] = h;
                    lw[u] = packbf(v0 - __uint_as_float(h << 16),
                                   v1 - __uint_as_float(h & 0xffff0000u));
                }
                *(uint4*)((char*)g_hh + (size_t)e * 128 + cb * 2) = make_uint4(hw[0], hw[1], hw[2], hw[3]);
                *(uint4*)((char*)g_hl + (size_t)e * 128 + cb * 2) = make_uint4(lw[0], lw[1], lw[2], lw[3]);
            }
        }
    } else {
        if (ok) {
#pragma unroll
            for (int cb = 0; cb < 64; cb += 4) {
                float4 v = make_float4(myE[cb], myE[cb + 1], myE[cb + 2], myE[cb + 3]);
                *(float4*)(outP + (size_t)e * 64 + cb) = v;
            }
        }
    }
    if (tid < 64) {
        float s_ = 0.f, q_ = 0.f;
#pragma unroll 4
        for (int r = 0; r < 128; r++) {
            float x = sE[r * 65 + tid];
            s_ += x;
            q_ += x * x;
        }
        atomicAdd(&g_sum[LAYER][tid], s_);
        atomicAdd(&g_sq[LAYER][tid], q_);
    }
}

extern "C" void kernel_launch(void* const* d_in, const int* in_sizes, int n_in,
                              void* d_out, int out_size) {
    const float* src = (const float*)d_in[0];
    const float* dst = (const float*)d_in[1];
    const float* eat = (const float*)d_in[2];
    const float* gat = (const float*)d_in[3];
    const void*  batch = d_in[4];
    const float* W1 = (const float*)d_in[5];
    const float* b1 = (const float*)d_in[6];
    const float* W2 = (const float*)d_in[7];
    const float* b2 = (const float*)d_in[8];
    const float* W3 = (const float*)d_in[9];
    const float* b3 = (const float*)d_in[10];
    const float* g1 = (const float*)d_in[11];
    const float* be1 = (const float*)d_in[12];
    const float* g2 = (const float*)d_in[13];
    const float* be2 = (const float*)d_in[14];
    const float* g3 = (const float*)d_in[15];
    const float* be3 = (const float*)d_in[16];

    int E = in_sizes[0] / 64;
    int G = in_sizes[3] / 64;
    float Einv = 1.0f / (float)E;
    float* out = (float*)d_out;
    int nt = (E + 127) >> 7;

    const int SM1 = 65536 + 33280 + 1024;   // 99,840
    const int SMN = 16384 + 33280 + 1024;   // 50,688
    cudaFuncSetAttribute(mma_layer<4, 0>, cudaFuncAttributeMaxDynamicSharedMemorySize, SM1);
    cudaFuncSetAttribute(mma_layer<1, 1>, cudaFuncAttributeMaxDynamicSharedMemorySize, SMN);
    cudaFuncSetAttribute(mma_layer<1, 2>, cudaFuncAttributeMaxDynamicSharedMemorySize, SMN);

    prep_kernel<<<16, 256>>>(W1, batch, E, G);

    // L1: concat(src,dest,edge,global[batch]) @ W1 + b1 -> relu -> hh/hl, stats[0]
    mma_layer<4, 0><<<nt, 128, SM1>>>(src, dst, eat, gat, batch, b1, out, E, G);
    fold_kernel<0><<<1, 64>>>(W2, b2, g1, be1, Einv);

    // L2: h @ W2' + b2' -> relu -> hh/hl, stats[1]
    mma_layer<1, 1><<<nt, 128, SMN>>>(src, dst, eat, gat, batch, b1, out, E, G);
    fold_kernel<1><<<1, 64>>>(W3, b3, g2, be2, Einv);

    // L3: h @ W3' + b3' -> relu -> d_out (pre-BN), stats[2]
    mma_layer<1, 2><<<nt, 128, SMN>>>(src, dst, eat, gat, batch, b1, out, E, G);
    fin_kernel<<<1, 64>>>(g3, be3, Einv);

    affine_kernel<<<4096, 256>>>(out, E * 16);
}